// round 9
// baseline (speedup 1.0000x reference)
#include <cuda_runtime.h>
#include <cstdint>

#define DEPTH    3
#define MARGIN   0.1f
#define BETA     0.5f
#define MAXN     16384          // max tokens (B*T); actual 2048
#define MAXWIDTH 262144         // max 2*V; actual 64000
#define TPB      256

// ---- device scratch (allocation-free; zero-initialized at module load;
//      g_hist restored to zero and g_done reset by the winner block) ----
__device__ int      g_hist[DEPTH * MAXWIDTH];
__device__ int      g_hash[DEPTH * MAXN];
__device__ float    g_row_nll [MAXN];   // masked log(p_target)
__device__ float    g_row_mask[MAXN];   // valid flag
__device__ float    g_row_rerr[MAXN];   // max(p_idk - p_target + MARGIN, 0)
__device__ unsigned g_done;

// fast softplus for the bulk sum (MUFU EX2/LG2 path)
__device__ __forceinline__ float softplus_fast(float x) {
    float e = __expf(-fabsf(x));
    return fmaxf(x, 0.0f) + __logf(1.0f + e);
}
// precise softplus for the two per-row scalars feeding log()
__device__ __forceinline__ float softplus_precise(float x) {
    float e = expf(-fabsf(x));
    return fmaxf(x, 0.0f) + log1pf(e);
}

// RELEASE-only atomic: publishes this block's prior writes (via the
// preceding bar.sync, cumulatively) WITHOUT acquire semantics — so no
// per-block L1D invalidate. R4 (__threadfence) and R8 (atom.acq_rel) both
// throttled the stream to 53.9% DRAM; acquire is the poison, not release.
__device__ __forceinline__ unsigned atom_add_release(unsigned* p, unsigned v) {
    unsigned old;
    asm volatile("atom.add.release.gpu.global.u32 %0, [%1], %2;"
                 : "=r"(old) : "l"(p), "r"(v) : "memory");
    return old;
}
__device__ __forceinline__ void fence_acq_rel_gpu() {
    asm volatile("fence.acq_rel.gpu;" ::: "memory");
}

// ---------------- single fused kernel ----------------
// Blocks [0, N):     stream one row each (only pass over the big tensor),
//                    write per-row nll/mask/rerr. Never touch g_hist.
// Blocks [N, total): count-min hashing + histogram atomics (overlapped;
//                    g_hist is written only here, read only by the winner).
// Winner (last to arrive): count-min query + deterministic fixed-order
//                    reduction + output + histogram restore + reset.
__global__ void __launch_bounds__(TPB) fused_kernel(const float* __restrict__ logits,
                                                    const long long* __restrict__ targets,
                                                    const long long* __restrict__ inputs,
                                                    const long long* __restrict__ salts,
                                                    float* __restrict__ out,
                                                    int N, int V, int vec_ok,
                                                    unsigned total_blocks) {
    const int bid  = blockIdx.x;
    const int tid  = threadIdx.x;
    const int lane = tid & 31, wid = tid >> 5;
    __shared__ float warp_sums[TPB / 32];

    if (bid >= N) {
        // ---- hash duty block ----
        int n = (bid - N) * TPB + tid;
        if (n < N) {
            long long width = 2LL * V;
            long long combined = inputs[n] * 31337LL + targets[n] * 2654435769LL;
            long long cm = combined % width;
            if (cm < 0) cm += width;
            int cmi = (int)cm, w = (int)width;
#pragma unroll
            for (int d = 0; d < DEPTH; d++) {
                int sm = (int)(salts[d] % width);   // salts >= 0
                int h = cmi + sm;
                if (h >= w) h -= w;
                g_hash[d * MAXN + n] = h;
                atomicAdd(&g_hist[d * MAXWIDTH + h], 1);
            }
        }
    } else {
        // ---- streaming row block (identical to R3's proven loop) ----
        const int r = bid;
        const float* row = logits + (size_t)r * V;

        float acc = 0.0f;
        if (vec_ok) {
            const float4* row4 = reinterpret_cast<const float4*>(row);
            const int n4 = V >> 2;
#pragma unroll 4
            for (int i = tid; i < n4; i += TPB) {
                float4 v = row4[i];
                acc += softplus_fast(v.x);
                acc += softplus_fast(v.y);
                acc += softplus_fast(v.z);
                acc += softplus_fast(v.w);
            }
        } else {
            for (int i = tid; i < V; i += TPB)
                acc += softplus_fast(row[i]);
        }

#pragma unroll
        for (int off = 16; off > 0; off >>= 1)
            acc += __shfl_xor_sync(0xFFFFFFFFu, acc, off);
        if (lane == 0) warp_sums[wid] = acc;
        __syncthreads();

        if (tid == 0) {
            float S = 0.0f;
#pragma unroll
            for (int w = 0; w < TPB / 32; w++) S += warp_sums[w];

            long long t = targets[r];
            bool valid  = (t != -1);
            int ti = (t >= 0 && t < V) ? (int)t : 0;
            float spt = softplus_precise(row[ti]);
            float spi = softplus_precise(row[0]);

            float scale = fminf(1.0f / (S + 1e-6f), 1.0f);
            float rem   = fmaxf(1.0f - S * scale, 0.0f);
            float p_t   = spt * scale + ((t == 0) ? rem : 0.0f);
            float p_i   = spi * scale + rem;

            g_row_nll [r] = valid ? logf(fmaxf(p_t, 1e-10f)) : 0.0f;
            g_row_mask[r] = valid ? 1.0f : 0.0f;
            g_row_rerr[r] = fmaxf(p_i - p_t + MARGIN, 0.0f);
        }
    }

    // ---- last-block election (release-only; no L1 invalidate) ----
    __shared__ unsigned s_last;
    __syncthreads();   // orders all block threads' writes before the release
    if (tid == 0)
        s_last = (atom_add_release(&g_done, 1u) == total_blocks - 1u);
    __syncthreads();
    if (!s_last) return;

    // ================= tail: runs in exactly one block =================
    fence_acq_rel_gpu();   // single acquire, one block only
    __syncthreads();

    // Query phase: batched two-wave loads (hashes first, then histogram
    // gathers); all via __ldcg (L2-direct, immune to stale L1).
    float nll_sum = 0.0f, mask_sum = 0.0f, basis_sum = 0.0f;

    for (int base = 0; base < N; base += TPB * 4) {
        int   h[4][DEPTH];
        float rr[4];
#pragma unroll
        for (int k = 0; k < 4; k++) {
            int n = base + k * TPB + tid;
            if (n < N) {
                nll_sum  += __ldcg(&g_row_nll[n]);
                mask_sum += __ldcg(&g_row_mask[n]);
                rr[k]     = __ldcg(&g_row_rerr[n]);
#pragma unroll
                for (int d = 0; d < DEPTH; d++)
                    h[k][d] = __ldcg(&g_hash[d * MAXN + n]);
            }
        }
#pragma unroll
        for (int k = 0; k < 4; k++) {
            int n = base + k * TPB + tid;
            if (n < N) {
                int c0 = __ldcg(&g_hist[0 * MAXWIDTH + h[k][0]]);
                int c1 = __ldcg(&g_hist[1 * MAXWIDTH + h[k][1]]);
                int c2 = __ldcg(&g_hist[2 * MAXWIDTH + h[k][2]]);
                int c  = min(c0, min(c1, c2));
                basis_sum += rr[k] * tanhf((float)c * 0.1f);
            }
        }
    }

    __syncthreads();   // all queries done before any restore decrements

    // Restore histogram to zero by replaying hashes (fire-and-forget).
    for (int i = tid; i < DEPTH * N; i += TPB) {
        int d = i / N, n = i - d * N;
        atomicSub(&g_hist[d * MAXWIDTH + __ldcg(&g_hash[d * MAXN + n])], 1);
    }

    // Deterministic fixed-order reduction (overlaps restore latency).
    __shared__ float s0[TPB / 32], s1[TPB / 32], s2[TPB / 32];
#pragma unroll
    for (int off = 16; off > 0; off >>= 1) {
        nll_sum   += __shfl_xor_sync(0xFFFFFFFFu, nll_sum,   off);
        mask_sum  += __shfl_xor_sync(0xFFFFFFFFu, mask_sum,  off);
        basis_sum += __shfl_xor_sync(0xFFFFFFFFu, basis_sum, off);
    }
    if (lane == 0) { s0[wid] = nll_sum; s1[wid] = mask_sum; s2[wid] = basis_sum; }
    __syncthreads();
    if (tid == 0) {
        float a = 0, b = 0, c = 0;
#pragma unroll
        for (int w = 0; w < TPB / 32; w++) { a += s0[w]; b += s1[w]; c += s2[w]; }
        out[0] = -a / fmaxf(b, 1.0f) + BETA * (c / (float)N);
        g_done = 0;    // reset for next replay (kernel boundary publishes it)
    }
}

extern "C" void kernel_launch(void* const* d_in, const int* in_sizes, int n_in,
                              void* d_out, int out_size) {
    // Resolve pointers by element count (robust to metadata ordering):
    //   salts: size == DEPTH; logits: largest; targets then inputs (relative order).
    const float*     logits  = nullptr;
    const long long* salts   = nullptr;
    const long long* tok[2]  = {nullptr, nullptr};
    int ntok_arrays = 0;
    long long logits_size = 0;
    int N = 0;

    for (int i = 0; i < n_in; i++) {
        long long sz = in_sizes[i];
        if (sz == DEPTH) {
            salts = (const long long*)d_in[i];
        } else if (sz > 1000000) {
            logits = (const float*)d_in[i];
            logits_size = sz;
        } else {
            if (ntok_arrays < 2) tok[ntok_arrays] = (const long long*)d_in[i];
            ntok_arrays++;
            N = (int)sz;
        }
    }
    const long long* targets = tok[0];
    const long long* inputs  = tok[1];

    int V = (N > 0) ? (int)(logits_size / N) : 0;
    float* out = (float*)d_out;

    int vec_ok = (((uintptr_t)logits & 15) == 0) && (V % 4 == 0);
    int hash_blocks = (N + TPB - 1) / TPB;
    unsigned total = (unsigned)(N + hash_blocks);

    fused_kernel<<<total, TPB>>>(logits, targets, inputs, salts, out,
                                 N, V, vec_ok, total);
}

// round 10
// speedup vs baseline: 1.3385x; 1.3385x over previous
#include <cuda_runtime.h>
#include <cstdint>

#define DEPTH    3
#define MARGIN   0.1f
#define BETA     0.5f
#define MAXN     16384          // max tokens (B*T); actual 2048
#define MAXWIDTH 262144         // max 2*V; actual 64000
#define TPB      256

// ---- device scratch (allocation-free; zero-initialized at module load;
//      g_hist restored to zero by final_kernel every invocation) ----
// NOTE: the count-min sketch is algebraically degenerate: salts are a common
// shift per depth, so min over depths == multiplicity of (combined % width).
// One histogram row suffices; salts never reach device code.
__device__ int   g_hist[MAXWIDTH];
__device__ int   g_cm  [MAXN];       // combined % width per token
__device__ float g_row_nll [MAXN];   // masked log(p_target)
__device__ float g_row_mask[MAXN];   // valid flag
__device__ float g_row_rerr[MAXN];   // max(p_idk - p_target + MARGIN, 0)

// fast softplus for the bulk sum (MUFU EX2/LG2 path)
__device__ __forceinline__ float softplus_fast(float x) {
    float e = __expf(-fabsf(x));
    return fmaxf(x, 0.0f) + __logf(1.0f + e);
}
// precise softplus for the two per-row scalars feeding log()
__device__ __forceinline__ float softplus_precise(float x) {
    float e = expf(-fabsf(x));
    return fmaxf(x, 0.0f) + log1pf(e);
}

// ---------------- kernel 1: stream + per-row epilogue + hashing ----------
// Blocks [0, N):     one block per row; the only pass over the big tensor.
// Blocks [N, total): token hashing + histogram atomics (overlapped; the
//                    histogram is only read by the next kernel).
// NO grid-wide election: R4/R8/R9 showed per-block end-of-kernel atomics
// throttle the stream from ~6.5 TB/s to 4.2 TB/s.
__global__ void __launch_bounds__(TPB) row_kernel(const float* __restrict__ logits,
                                                  const long long* __restrict__ targets,
                                                  const long long* __restrict__ inputs,
                                                  int N, int V, int vec_ok) {
    const int bid = blockIdx.x;
    const int tid = threadIdx.x;

    if (bid >= N) {
        // ---- hash duty block ----
        int n = (bid - N) * TPB + tid;
        if (n < N) {
            long long width = 2LL * V;
            long long combined = inputs[n] * 31337LL + targets[n] * 2654435769LL;
            long long cm = combined % width;
            if (cm < 0) cm += width;
            int cmi = (int)cm;
            g_cm[n] = cmi;
            atomicAdd(&g_hist[cmi], 1);
        }
        return;
    }

    // ---- streaming row block ----
    const int r = bid;
    const float* row = logits + (size_t)r * V;

    float acc = 0.0f;
    if (vec_ok) {
        const float4* row4 = reinterpret_cast<const float4*>(row);
        const int n4 = V >> 2;
#pragma unroll 4
        for (int i = tid; i < n4; i += TPB) {
            float4 v = __ldcs(&row4[i]);   // single-use stream: evict-first
            acc += softplus_fast(v.x);
            acc += softplus_fast(v.y);
            acc += softplus_fast(v.z);
            acc += softplus_fast(v.w);
        }
    } else {
        for (int i = tid; i < V; i += TPB)
            acc += softplus_fast(row[i]);
    }

    __shared__ float warp_sums[TPB / 32];
#pragma unroll
    for (int off = 16; off > 0; off >>= 1)
        acc += __shfl_xor_sync(0xFFFFFFFFu, acc, off);
    int lane = tid & 31, wid = tid >> 5;
    if (lane == 0) warp_sums[wid] = acc;
    __syncthreads();

    if (tid == 0) {
        float S = 0.0f;
#pragma unroll
        for (int w = 0; w < TPB / 32; w++) S += warp_sums[w];

        long long t = targets[r];
        bool valid  = (t != -1);
        int ti = (t >= 0 && t < V) ? (int)t : 0;
        float spt = softplus_precise(row[ti]);
        float spi = softplus_precise(row[0]);

        float scale = fminf(1.0f / (S + 1e-6f), 1.0f);
        float rem   = fmaxf(1.0f - S * scale, 0.0f);
        float p_t   = spt * scale + ((t == 0) ? rem : 0.0f);
        float p_i   = spi * scale + rem;

        g_row_nll [r] = valid ? logf(fmaxf(p_t, 1e-10f)) : 0.0f;
        g_row_mask[r] = valid ? 1.0f : 0.0f;
        g_row_rerr[r] = fmaxf(p_i - p_t + MARGIN, 0.0f);
    }
}

// ---------------- kernel 2: query + reduction + restore (PDL) -----------
// Launched with programmatic stream serialization: it is dispatched while
// row_kernel still runs (hiding launch latency) and blocks on
// cudaGridDependencySynchronize() until row_kernel fully completes.
__global__ void __launch_bounds__(1024) final_kernel(float* __restrict__ out, int N) {
#if __CUDA_ARCH__ >= 900
    cudaGridDependencySynchronize();
#endif
    const int tid = threadIdx.x;
    float nll_sum = 0.0f, mask_sum = 0.0f, basis_sum = 0.0f;

    // batched loads: issue all independent loads first, then the dependent
    // histogram gathers (2 latency waves instead of a per-token chain)
    for (int base = 0; base < N; base += 1024 * 2) {
        int   cm[2];
        float rr[2];
#pragma unroll
        for (int k = 0; k < 2; k++) {
            int n = base + k * 1024 + tid;
            if (n < N) {
                nll_sum  += g_row_nll[n];
                mask_sum += g_row_mask[n];
                rr[k]     = g_row_rerr[n];
                cm[k]     = g_cm[n];
            }
        }
#pragma unroll
        for (int k = 0; k < 2; k++) {
            int n = base + k * 1024 + tid;
            if (n < N) {
                int c = g_hist[cm[k]];
                basis_sum += rr[k] * tanhf((float)c * 0.1f);
            }
        }
    }

    __syncthreads();   // all queries done before any restore decrements

    // restore histogram to zero by replaying hashes (graph-replay safe)
    for (int n = tid; n < N; n += 1024)
        atomicSub(&g_hist[g_cm[n]], 1);

    // deterministic fixed-order reduction
    __shared__ float s0[32], s1[32], s2[32];
#pragma unroll
    for (int off = 16; off > 0; off >>= 1) {
        nll_sum   += __shfl_xor_sync(0xFFFFFFFFu, nll_sum,   off);
        mask_sum  += __shfl_xor_sync(0xFFFFFFFFu, mask_sum,  off);
        basis_sum += __shfl_xor_sync(0xFFFFFFFFu, basis_sum, off);
    }
    int lane = tid & 31, wid = tid >> 5;
    if (lane == 0) { s0[wid] = nll_sum; s1[wid] = mask_sum; s2[wid] = basis_sum; }
    __syncthreads();
    if (tid == 0) {
        float a = 0, b = 0, c = 0;
#pragma unroll
        for (int w = 0; w < 32; w++) { a += s0[w]; b += s1[w]; c += s2[w]; }
        out[0] = -a / fmaxf(b, 1.0f) + BETA * (c / (float)N);
    }
}

extern "C" void kernel_launch(void* const* d_in, const int* in_sizes, int n_in,
                              void* d_out, int out_size) {
    // Resolve pointers by element count (robust to metadata ordering):
    //   salts: size == DEPTH (unused on device — algebraically eliminated);
    //   logits: largest; targets then inputs (relative order).
    const float*     logits  = nullptr;
    const long long* tok[2]  = {nullptr, nullptr};
    int ntok_arrays = 0;
    long long logits_size = 0;
    int N = 0;

    for (int i = 0; i < n_in; i++) {
        long long sz = in_sizes[i];
        if (sz == DEPTH) {
            // salts — not needed (common shift per depth cancels in the min)
        } else if (sz > 1000000) {
            logits = (const float*)d_in[i];
            logits_size = sz;
        } else {
            if (ntok_arrays < 2) tok[ntok_arrays] = (const long long*)d_in[i];
            ntok_arrays++;
            N = (int)sz;
        }
    }
    const long long* targets = tok[0];
    const long long* inputs  = tok[1];

    int V = (N > 0) ? (int)(logits_size / N) : 0;
    float* out = (float*)d_out;

    int vec_ok = (((uintptr_t)logits & 15) == 0) && (V % 4 == 0);
    int hash_blocks = (N + TPB - 1) / TPB;

    row_kernel<<<N + hash_blocks, TPB>>>(logits, targets, inputs, N, V, vec_ok);

    // PDL launch of the epilogue: dispatch overlaps row_kernel execution.
    cudaLaunchAttribute attrs[1];
    attrs[0].id = cudaLaunchAttributeProgrammaticStreamSerialization;
    attrs[0].val.programmaticStreamSerializationAllowed = 1;
    cudaLaunchConfig_t cfg = {};
    cfg.gridDim  = dim3(1, 1, 1);
    cfg.blockDim = dim3(1024, 1, 1);
    cfg.dynamicSmemBytes = 0;
    cfg.stream = 0;
    cfg.attrs = attrs;
    cfg.numAttrs = 1;
    cudaLaunchKernelEx(&cfg, final_kernel, out, N);
}